// round 14
// baseline (speedup 1.0000x reference)
#include <cuda_runtime.h>
#include <cuda_fp16.h>
#include <cstdint>
#include <math.h>

// Problem dimensions (fixed by the reference)
#define BATCH 8
#define SEQ   8192
#define DIM   512
#define HID   512
#define OUTD  512
#define MROWS (BATCH*SEQ)      // 65536
#define HCH   64               // half-chunk rows (scan granularity)
#define NHC   (SEQ/HCH)        // 128 half-chunks

// ---------------------------------------------------------------------------
// Device scratch (no runtime allocation allowed)
// ---------------------------------------------------------------------------
static __device__ __half g_lch[(size_t)MROWS*HID];      // log_coeffs (fp16)
static __device__ __half g_lvh[(size_t)MROWS*HID];      // log_values (fp16)
static __device__ float g_A  [(size_t)BATCH*NHC*HID];   // half-chunk sum log_coeffs
static __device__ float g_LVc[(size_t)BATCH*NHC*HID];   // half-chunk log-value
static __device__ __half g_xh [(size_t)MROWS*DIM];      // x     (fp16)
static __device__ __half g_wh [(size_t)2*HID*DIM];      // W_hg  (fp16)
static __device__ __half g_wo [(size_t)OUTD*HID];       // W_out (fp16)

// ---------------------------------------------------------------------------
// PTX helpers (sm_80+ only; no 'a'-suffix features)
// ---------------------------------------------------------------------------
__device__ __forceinline__ uint32_t smem_u32(const void* p) {
    uint32_t a;
    asm("{ .reg .u64 t; cvta.to.shared.u64 t, %1; cvt.u32.u64 %0, t; }" : "=r"(a) : "l"(p));
    return a;
}

#define CP_ASYNC16(dst, src) \
    asm volatile("cp.async.cg.shared.global [%0], [%1], 16;" :: "r"(dst), "l"(src))
#define CP_COMMIT() asm volatile("cp.async.commit_group;" ::: "memory")
#define CP_WAIT(N)  asm volatile("cp.async.wait_group %0;" :: "n"(N) : "memory")

#define LDMX4(r0, r1, r2, r3, a) \
    asm volatile("ldmatrix.sync.aligned.m8n8.x4.shared.b16 {%0,%1,%2,%3}, [%4];" \
        : "=r"(r0), "=r"(r1), "=r"(r2), "=r"(r3) : "r"(a))

// fp16 MMA, fp32 accumulate
#define MMA16816(c0, c1, c2, c3, a0, a1, a2, a3, b0, b1) \
    asm volatile("mma.sync.aligned.m16n8k16.row.col.f32.f16.f16.f32 " \
        "{%0,%1,%2,%3}, {%4,%5,%6,%7}, {%8,%9}, {%0,%1,%2,%3};" \
        : "+f"(c0), "+f"(c1), "+f"(c2), "+f"(c3) \
        : "r"(a0), "r"(a1), "r"(a2), "r"(a3), "r"(b0), "r"(b1))

// ---------------------------------------------------------------------------
// Math helpers (fast MUFU path)
// ---------------------------------------------------------------------------
__device__ __forceinline__ float sp_f(float x) {
    return fmaxf(x, 0.0f) + __logf(1.0f + __expf(-fabsf(x)));
}
__device__ __forceinline__ float lae(float a, float b) {
    float m = fmaxf(a, b);
    return m + __logf(1.0f + __expf(-fabsf(a - b)));
}

// ---------------------------------------------------------------------------
// Single fused fp32 -> fp16 conversion for x, W_hg, W_out
// ---------------------------------------------------------------------------
#define NX4 ((size_t)MROWS*DIM/4)          // 8388608
#define NW4 ((size_t)2*HID*DIM/4)          // 131072
#define NO4 ((size_t)OUTD*HID/4)           // 65536

__global__ __launch_bounds__(256) void cvt_all(const float* __restrict__ x,
                                               const float* __restrict__ Whg,
                                               const float* __restrict__ Wout) {
    const size_t i = (size_t)blockIdx.x * blockDim.x + threadIdx.x;
    const float* src;
    __half* dst;
    size_t k;
    if (i < NX4)            { src = x;    dst = g_xh; k = i; }
    else if (i < NX4 + NW4) { src = Whg;  dst = g_wh; k = i - NX4; }
    else                    { src = Wout; dst = g_wo; k = i - NX4 - NW4; }
    float4 v = ((const float4*)src)[k];
    ((__half2*)dst)[2*k]   = __floats2half2_rn(v.x, v.y);
    ((__half2*)dst)[2*k+1] = __floats2half2_rn(v.z, v.w);
}

// ---------------------------------------------------------------------------
// GEMM1 mainloop (unchanged from R13): block 64Mx128N, 128 threads, kc=64,
// 2-stage cp.async, 4 CTAs/SM. acc += A*B (fp32 accumulate).
// SMEM stage: A [0,9216)  B [9216,27648), row stride 144B.
// INTERLEAVE: B-tile n-row r -> W_hg row (even: hidden, odd: gate).
// ---------------------------------------------------------------------------
#define ROWB    144
#define ARR_A   (64*ROWB)       // 9216
#define ARR_BT  (128*ROWB)      // 18432
#define STG_B   (ARR_A+ARR_BT)  // 27648
#define SMEM_G1 (2*STG_B)       // 55296

__device__ __forceinline__ void gemm1_mainloop(const __half* __restrict__ A,
                                               const __half* __restrict__ B,
                                               int m0, int nb, uint32_t sbase,
                                               float acc[4][4][4]) {
    const int tid  = threadIdx.x;
    const int lane = tid & 31;
    const int wid  = tid >> 5;
    const int wn   = wid * 32;

#pragma unroll
    for (int mi = 0; mi < 4; mi++)
#pragma unroll
        for (int ni = 0; ni < 4; ni++)
#pragma unroll
            for (int e = 0; e < 4; e++) acc[mi][ni][e] = 0.0f;

    uint32_t a_off[4], b_off[2];
#pragma unroll
    for (int mi = 0; mi < 4; mi++)
        a_off[mi] = (uint32_t)((mi * 16 + (lane & 15)) * ROWB
                               + ((lane & 16) ? 16 : 0));
#pragma unroll
    for (int p = 0; p < 2; p++)
        b_off[p] = (uint32_t)(ARR_A
                   + (wn + p * 16 + (lane & 7) + ((lane & 16) ? 8 : 0)) * ROWB
                   + ((lane & 8) ? 16 : 0));

    auto load_stage = [&](int j, int s) {
        const uint32_t st = sbase + s * STG_B;
        const int k0 = j * 64;
#pragma unroll
        for (int i = 0; i < 4; i++) {
            const int idx = tid + i * 128;
            const int r = idx >> 3, c = idx & 7;
            CP_ASYNC16(st + (uint32_t)(r * ROWB + c * 16),
                       (const void*)(A + (size_t)(m0 + r) * 512 + k0 + c * 8));
        }
#pragma unroll
        for (int i = 0; i < 8; i++) {
            const int idx = tid + i * 128;
            const int r = idx >> 3, c = idx & 7;
            const int wr = (r & 1) ? (512 + nb + (r >> 1)) : (nb + (r >> 1));
            CP_ASYNC16(st + (uint32_t)(ARR_A + r * ROWB + c * 16),
                       (const void*)(B + (size_t)wr * 512 + k0 + c * 8));
        }
        CP_COMMIT();
    };

    load_stage(0, 0);

    for (int j = 0; j < 8; j++) {
        CP_WAIT(0);
        __syncthreads();
        if (j + 1 < 8) load_stage(j + 1, (j + 1) & 1);

        const uint32_t st = sbase + (j & 1) * STG_B;
#pragma unroll
        for (int s = 0; s < 4; s++) {
            const uint32_t sk = st + (uint32_t)(s * 32);
            uint32_t bh[4][2], ah[4][4];
            LDMX4(bh[0][0], bh[0][1], bh[1][0], bh[1][1], sk + b_off[0]);
            LDMX4(bh[2][0], bh[2][1], bh[3][0], bh[3][1], sk + b_off[1]);
#pragma unroll
            for (int mi = 0; mi < 4; mi++)
                LDMX4(ah[mi][0], ah[mi][1], ah[mi][2], ah[mi][3], sk + a_off[mi]);
#pragma unroll
            for (int mi = 0; mi < 4; mi++)
#pragma unroll
                for (int ni = 0; ni < 4; ni++)
                    MMA16816(acc[mi][ni][0], acc[mi][ni][1], acc[mi][ni][2], acc[mi][ni][3],
                             ah[mi][0], ah[mi][1], ah[mi][2], ah[mi][3],
                             bh[ni][0], bh[ni][1]);
        }
    }
    __syncthreads();
}

// ---------------------------------------------------------------------------
// GEMM1: hg = x @ W_hg^T, fused lc/lv epilogue (fp16) + half-chunk summaries.
// Block = 64 m-rows x 64 channels. Grid (8, 1024). 4 CTAs/SM.
// ---------------------------------------------------------------------------
__global__ __launch_bounds__(128, 4)
void gemm1_mma() {
    extern __shared__ __align__(128) char smem[];
    const uint32_t sbase = smem_u32(smem);
    const int m0 = blockIdx.y * 64;
    const int nb = blockIdx.x * 64;

    float acc[4][4][4];
    gemm1_mainloop(g_xh, g_wh, m0, nb, sbase, acc);

    float* lcs = (float*)smem;                      // [64][76]
    float* lvs = lcs + 64 * 76;                     // [64][76]
    float* segA  = (float*)(smem + 40960);          // [2][64]
    float* segLV = segA + 128;                      // [2][64]
    const int tid = threadIdx.x, lane = tid & 31, wid = tid >> 5;
    const int wn = wid * 32;

#pragma unroll
    for (int mi = 0; mi < 4; mi++) {
#pragma unroll
        for (int ni = 0; ni < 4; ni++) {
            const int j  = (wn >> 1) + ni * 4 + (lane & 3);   // channel 0..63
            const int r0 = mi * 16 + (lane >> 2);
#pragma unroll
            for (int e = 0; e < 2; e++) {
                const int r = r0 + e * 8;
                const float hv = acc[mi][ni][2*e];
                const float gv = acc[mi][ni][2*e + 1];
                const float lgv = (hv >= 0.0f) ? __logf(hv + 0.5f) : -sp_f(-hv);
                lcs[r * 76 + j] = -sp_f(gv);
                lvs[r * 76 + j] = lgv - sp_f(-gv);
            }
        }
    }
    __syncthreads();

    for (int idx = tid; idx < 1024; idx += 128) {
        const int r = idx >> 4, q = idx & 15;
        const size_t go = (size_t)(m0 + r) * HID + nb + q * 4;
        float4 vc = *(float4*)&lcs[r * 76 + q * 4];
        float4 vv = *(float4*)&lvs[r * 76 + q * 4];
        __half2 c2[2] = { __floats2half2_rn(vc.x, vc.y), __floats2half2_rn(vc.z, vc.w) };
        __half2 v2[2] = { __floats2half2_rn(vv.x, vv.y), __floats2half2_rn(vv.z, vv.w) };
        *(uint2*)(g_lch + go) = *(uint2*)c2;
        *(uint2*)(g_lvh + go) = *(uint2*)v2;
    }

    {
        const int j = tid & 63, seg = tid >> 6;
        float Acc = 0.0f, LV = -1e30f;
        for (int r = seg * 32; r < seg * 32 + 32; r++) {
            const float lc = lcs[r * 76 + j];
            const float lv = lvs[r * 76 + j];
            LV = lae(lc + LV, lv);
            Acc += lc;
        }
        segA [seg * 64 + j] = Acc;
        segLV[seg * 64 + j] = LV;
    }
    __syncthreads();
    if (tid < 64) {
        const float A2  = segA [64 + tid];
        const float LV2 = segLV[64 + tid];
        float Acc = segA[tid] + A2;
        float LV  = lae(segLV[tid] + A2, LV2);
        const int b = m0 / SEQ, hc = (m0 % SEQ) / HCH;
        const size_t si = ((size_t)(b * NHC + hc)) * HID + nb + tid;
        g_A[si]   = Acc;
        g_LVc[si] = LV;
    }
}

// ---------------------------------------------------------------------------
// FUSED scan + GEMM2. Block = one (batch, half-chunk) = 64 m-rows; 128 thr.
// Phase 1: inter-chunk prefix (from L2-resident g_A/g_LVc) + 64-step replay,
//          h written as fp16 into SMEM (row stride 1040B; 1040/4 mod 32 = 4
//          -> conflict-free ldmatrix and 2-way-max scan stores).
// Phase 2: out[m0..m0+63][:] = h_smem @ W_out^T. Flattened 32-chunk
//          double-buffered pipeline (4 N-tiles x 8 k-chunks), epilogue
//          store + acc reset every 8 chunks.
// SMEM: h tile [0, 66560) ; B stages [66560, 66560+2*18432) = 103424B.
// ---------------------------------------------------------------------------
#define HT_ROWB  1040
#define HT_BYTES (64*HT_ROWB)             // 66560
#define STG2_B   ARR_BT                   // 18432 (B only)
#define SMEM_SG2 (HT_BYTES + 2*STG2_B)    // 103424

__global__ __launch_bounds__(128, 2)
void scan_gemm2(float* __restrict__ out, float* __restrict__ out_hn) {
    extern __shared__ __align__(128) char smem[];
    const uint32_t sbase = smem_u32(smem);
    const int b = blockIdx.y, cid = blockIdx.x;       // cid 0..127
    const int tid = threadIdx.x, lane = tid & 31, wid = tid >> 5;
    const int m0 = b * SEQ + cid * HCH;               // global row base

    // ---------------- Phase 1: scan ----------------
    {
        const int ch = tid * 4;
        // prefix over half-chunks [0, cid)
        float4 lh = make_float4(-1e30f, -1e30f, -1e30f, -1e30f);
        size_t si = ((size_t)(b * NHC)) * HID + ch;
        for (int c = 0; c < cid; c++, si += HID) {
            const float4 A4 = *(const float4*)(g_A + si);
            const float4 L4 = *(const float4*)(g_LVc + si);
            lh.x = lae(A4.x + lh.x, L4.x);
            lh.y = lae(A4.y + lh.y, L4.y);
            lh.z = lae(A4.z + lh.z, L4.z);
            lh.w = lae(A4.w + lh.w, L4.w);
        }
        // replay, software pipelined; h -> smem
        size_t base = (size_t)m0 * HID + ch;
        float4 hv = make_float4(0.f, 0.f, 0.f, 0.f);
        uint2 pc = *(const uint2*)(g_lch + base);
        uint2 pv = *(const uint2*)(g_lvh + base);
#pragma unroll 4
        for (int t = 0; t < HCH; t++) {
            uint2 npc, npv;
            if (t + 1 < HCH) {
                npc = *(const uint2*)(g_lch + base + HID);
                npv = *(const uint2*)(g_lvh + base + HID);
            }
            const float2 c01 = __half22float2(*(const __half2*)&pc.x);
            const float2 c23 = __half22float2(*(const __half2*)&pc.y);
            const float2 v01 = __half22float2(*(const __half2*)&pv.x);
            const float2 v23 = __half22float2(*(const __half2*)&pv.y);
            lh.x = lae(c01.x + lh.x, v01.x);
            lh.y = lae(c01.y + lh.y, v01.y);
            lh.z = lae(c23.x + lh.z, v23.x);
            lh.w = lae(c23.y + lh.w, v23.y);
            hv.x = __expf(lh.x); hv.y = __expf(lh.y);
            hv.z = __expf(lh.z); hv.w = __expf(lh.w);
            __half2 h2[2] = { __floats2half2_rn(hv.x, hv.y), __floats2half2_rn(hv.z, hv.w) };
            *(uint2*)(smem + t * HT_ROWB + ch * 2) = *(uint2*)h2;
            pc = npc; pv = npv;
            base += HID;
        }
        if (cid == NHC - 1)
            *(float4*)(out_hn + b * HID + ch) = hv;
    }
    __syncthreads();    // h tile visible to all warps

    // ---------------- Phase 2: GEMM2 from smem h ----------------
    const int wn = wid * 32;
    uint32_t a_off[4], b_off[2];
#pragma unroll
    for (int mi = 0; mi < 4; mi++)
        a_off[mi] = (uint32_t)((mi * 16 + (lane & 15)) * HT_ROWB
                               + ((lane & 16) ? 16 : 0));
#pragma unroll
    for (int p = 0; p < 2; p++)
        b_off[p] = (uint32_t)(HT_BYTES
                   + (wn + p * 16 + (lane & 7) + ((lane & 16) ? 8 : 0)) * ROWB
                   + ((lane & 8) ? 16 : 0));

    // chunk c (0..31): N-tile nbi = c>>3, k-chunk j = c&7
    auto load_chunk = [&](int c, int s) {
        const uint32_t st = sbase + HT_BYTES + s * STG2_B;
        const int nbase = (c >> 3) * 128;
        const int k0 = (c & 7) * 64;
#pragma unroll
        for (int i = 0; i < 8; i++) {          // 1024 16B-chunks
            const int idx = tid + i * 128;
            const int r = idx >> 3, cc = idx & 7;
            CP_ASYNC16(st + (uint32_t)(r * ROWB + cc * 16),
                       (const void*)(g_wo + (size_t)(nbase + r) * 512 + k0 + cc * 8));
        }
        CP_COMMIT();
    };

    float acc[4][4][4];
#pragma unroll
    for (int mi = 0; mi < 4; mi++)
#pragma unroll
        for (int ni = 0; ni < 4; ni++)
#pragma unroll
            for (int e = 0; e < 4; e++) acc[mi][ni][e] = 0.0f;

    load_chunk(0, 0);

    for (int c = 0; c < 32; c++) {
        CP_WAIT(0);
        __syncthreads();
        if (c + 1 < 32) load_chunk(c + 1, (c + 1) & 1);

        const uint32_t stB = sbase + HT_BYTES + (c & 1) * STG2_B;
        const uint32_t stA = sbase + (uint32_t)((c & 7) * 128);  // k0*2 bytes
#pragma unroll
        for (int s = 0; s < 4; s++) {
            const uint32_t skA = stA + (uint32_t)(s * 32);
            const uint32_t skB = stB + (uint32_t)(s * 32) - HT_BYTES + HT_BYTES; // plain
            uint32_t bh[4][2], ah[4][4];
            LDMX4(bh[0][0], bh[0][1], bh[1][0], bh[1][1], stB - HT_BYTES + HT_BYTES + (uint32_t)(s*32) + b_off[0] - HT_BYTES);
            LDMX4(bh[2][0], bh[2][1], bh[3][0], bh[3][1], stB - HT_BYTES + HT_BYTES + (uint32_t)(s*32) + b_off[1] - HT_BYTES);
#pragma unroll
            for (int mi = 0; mi < 4; mi++)
                LDMX4(ah[mi][0], ah[mi][1], ah[mi][2], ah[mi][3], skA + a_off[mi]);
#pragma unroll
            for (int mi = 0; mi < 4; mi++)
#pragma unroll
                for (int ni = 0; ni < 4; ni++)
                    MMA16816(acc[mi][ni][0], acc[mi][ni][1], acc[mi][ni][2], acc[mi][ni][3],
                             ah[mi][0], ah[mi][1], ah[mi][2], ah[mi][3],
                             bh[ni][0], bh[ni][1]);
            (void)skB;
        }

        if ((c & 7) == 7) {   // epilogue for N-tile nbi = c>>3
            const int nbase = (c >> 3) * 128;
#pragma unroll
            for (int mi = 0; mi < 4; mi++) {
#pragma unroll
                for (int ni = 0; ni < 4; ni++) {
                    const int col = nbase + wn + ni * 8 + (lane & 3) * 2;
                    const int r0  = m0 + mi * 16 + (lane >> 2);
                    *(float2*)(out + (size_t)r0 * OUTD + col)
                        = make_float2(acc[mi][ni][0], acc[mi][ni][1]);
                    *(float2*)(out + (size_t)(r0 + 8) * OUTD + col)
                        = make_float2(acc[mi][ni][2], acc[mi][ni][3]);
                    acc[mi][ni][0] = acc[mi][ni][1] = 0.0f;
                    acc[mi][ni][2] = acc[mi][ni][3] = 0.0f;
                }
            }
        }
    }
}

// ---------------------------------------------------------------------------
// Launch. Inputs: x f32 (8,8192,512) | is_init bool(8) | W_hg f32 (1024,512)
// | W_out f32 (512,512). Output: out f32 (B,S,O) ++ h_n f32 (B,1,H).
// ---------------------------------------------------------------------------
extern "C" void kernel_launch(void* const* d_in, const int* in_sizes, int n_in,
                              void* d_out, int out_size) {
    (void)in_sizes; (void)n_in; (void)out_size;
    const float* x    = (const float*)d_in[0];
    const float* Whg  = (const float*)d_in[2];
    const float* Wout = (const float*)d_in[3];
    float* out    = (float*)d_out;
    float* out_hn = out + (size_t)MROWS * OUTD;

    cudaFuncSetAttribute((const void*)gemm1_mma,
                         cudaFuncAttributeMaxDynamicSharedMemorySize, SMEM_G1);
    cudaFuncSetAttribute((const void*)scan_gemm2,
                         cudaFuncAttributeMaxDynamicSharedMemorySize, SMEM_SG2);

    // single fused fp16 conversion (x + both weights)
    cvt_all<<<(unsigned)((NX4 + NW4 + NO4) / 256), 256>>>(x, Whg, Wout);

    // GEMM1 (fp16, kc=64, 64x128 tiles, 4 CTAs/SM) + fused lc/lv + summaries
    gemm1_mma<<<dim3(HID / 64, MROWS / 64), 128, SMEM_G1>>>();

    // FUSED scan + GEMM2 (h stays in SMEM)
    scan_gemm2<<<dim3(NHC, BATCH), 128, SMEM_SG2>>>(out, out_hn);
}

// round 15
// speedup vs baseline: 1.0475x; 1.0475x over previous
#include <cuda_runtime.h>
#include <cuda_fp16.h>
#include <cstdint>
#include <math.h>

// Problem dimensions (fixed by the reference)
#define BATCH 8
#define SEQ   8192
#define DIM   512
#define HID   512
#define OUTD  512
#define MROWS (BATCH*SEQ)      // 65536
#define HCH   64               // half-chunk rows (scan granularity)
#define NHC   (SEQ/HCH)        // 128 half-chunks

// ---------------------------------------------------------------------------
// Device scratch (no runtime allocation allowed)
// g_lcv: interleaved lc/lv, 16B record per (row, 4-channel group):
//   [lc0 lc1 lc2 lc3 lv0 lv1 lv2 lv3] (fp16 each) at offset (m*HID+ch)*2
// ---------------------------------------------------------------------------
static __device__ __half g_lcv[(size_t)MROWS*HID*2];    // lc/lv interleaved
static __device__ float g_A  [(size_t)BATCH*NHC*HID];   // half-chunk sum log_coeffs
static __device__ float g_LVc[(size_t)BATCH*NHC*HID];   // half-chunk log-value
static __device__ __half g_xh [(size_t)MROWS*DIM];      // x     (fp16)
static __device__ __half g_hh [(size_t)MROWS*HID];      // h     (fp16)
static __device__ __half g_wh [(size_t)2*HID*DIM];      // W_hg  (fp16)
static __device__ __half g_wo [(size_t)OUTD*HID];       // W_out (fp16)

// ---------------------------------------------------------------------------
// PTX helpers (sm_80+ only; no 'a'-suffix features)
// ---------------------------------------------------------------------------
__device__ __forceinline__ uint32_t smem_u32(const void* p) {
    uint32_t a;
    asm("{ .reg .u64 t; cvta.to.shared.u64 t, %1; cvt.u32.u64 %0, t; }" : "=r"(a) : "l"(p));
    return a;
}

#define CP_ASYNC16(dst, src) \
    asm volatile("cp.async.cg.shared.global [%0], [%1], 16;" :: "r"(dst), "l"(src))
#define CP_COMMIT() asm volatile("cp.async.commit_group;" ::: "memory")
#define CP_WAIT(N)  asm volatile("cp.async.wait_group %0;" :: "n"(N) : "memory")

#define LDMX4(r0, r1, r2, r3, a) \
    asm volatile("ldmatrix.sync.aligned.m8n8.x4.shared.b16 {%0,%1,%2,%3}, [%4];" \
        : "=r"(r0), "=r"(r1), "=r"(r2), "=r"(r3) : "r"(a))

// fp16 MMA, fp32 accumulate
#define MMA16816(c0, c1, c2, c3, a0, a1, a2, a3, b0, b1) \
    asm volatile("mma.sync.aligned.m16n8k16.row.col.f32.f16.f16.f32 " \
        "{%0,%1,%2,%3}, {%4,%5,%6,%7}, {%8,%9}, {%0,%1,%2,%3};" \
        : "+f"(c0), "+f"(c1), "+f"(c2), "+f"(c3) \
        : "r"(a0), "r"(a1), "r"(a2), "r"(a3), "r"(b0), "r"(b1))

// ---------------------------------------------------------------------------
// Math helpers (fast MUFU path)
// ---------------------------------------------------------------------------
__device__ __forceinline__ float sp_f(float x) {
    return fmaxf(x, 0.0f) + __logf(1.0f + __expf(-fabsf(x)));
}
__device__ __forceinline__ float lae(float a, float b) {
    float m = fmaxf(a, b);
    return m + __logf(1.0f + __expf(-fabsf(a - b)));
}

// ---------------------------------------------------------------------------
// Single fused fp32 -> fp16 conversion for x, W_hg, W_out
// ---------------------------------------------------------------------------
#define NX4 ((size_t)MROWS*DIM/4)          // 8388608
#define NW4 ((size_t)2*HID*DIM/4)          // 131072
#define NO4 ((size_t)OUTD*HID/4)           // 65536

__global__ __launch_bounds__(256) void cvt_all(const float* __restrict__ x,
                                               const float* __restrict__ Whg,
                                               const float* __restrict__ Wout) {
    const size_t i = (size_t)blockIdx.x * blockDim.x + threadIdx.x;
    const float* src;
    __half* dst;
    size_t k;
    if (i < NX4)            { src = x;    dst = g_xh; k = i; }
    else if (i < NX4 + NW4) { src = Whg;  dst = g_wh; k = i - NX4; }
    else                    { src = Wout; dst = g_wo; k = i - NX4 - NW4; }
    float4 v = ((const float4*)src)[k];
    ((__half2*)dst)[2*k]   = __floats2half2_rn(v.x, v.y);
    ((__half2*)dst)[2*k+1] = __floats2half2_rn(v.z, v.w);
}

// ---------------------------------------------------------------------------
// GEMM1 mainloop: block 64Mx128N, 128 threads (4 warps, warp tile 64x32),
// K=512, kc=64, 2-stage cp.async, 4 CTAs/SM. acc += A*B (fp32 accumulate).
// SMEM stage: A [0,9216)  B [9216,27648), row stride 144B.
// INTERLEAVE: B-tile n-row r -> W_hg row (even: hidden, odd: gate).
// ---------------------------------------------------------------------------
#define ROWB    144
#define ARR_A   (64*ROWB)       // 9216
#define ARR_BT  (128*ROWB)      // 18432
#define STG_B   (ARR_A+ARR_BT)  // 27648
#define SMEM_G1 (2*STG_B)       // 55296

__device__ __forceinline__ void gemm1_mainloop(const __half* __restrict__ A,
                                               const __half* __restrict__ B,
                                               int m0, int nb, uint32_t sbase,
                                               float acc[4][4][4]) {
    const int tid  = threadIdx.x;
    const int lane = tid & 31;
    const int wid  = tid >> 5;
    const int wn   = wid * 32;

#pragma unroll
    for (int mi = 0; mi < 4; mi++)
#pragma unroll
        for (int ni = 0; ni < 4; ni++)
#pragma unroll
            for (int e = 0; e < 4; e++) acc[mi][ni][e] = 0.0f;

    uint32_t a_off[4], b_off[2];
#pragma unroll
    for (int mi = 0; mi < 4; mi++)
        a_off[mi] = (uint32_t)((mi * 16 + (lane & 15)) * ROWB
                               + ((lane & 16) ? 16 : 0));
#pragma unroll
    for (int p = 0; p < 2; p++)
        b_off[p] = (uint32_t)(ARR_A
                   + (wn + p * 16 + (lane & 7) + ((lane & 16) ? 8 : 0)) * ROWB
                   + ((lane & 8) ? 16 : 0));

    auto load_stage = [&](int j, int s) {
        const uint32_t st = sbase + s * STG_B;
        const int k0 = j * 64;
#pragma unroll
        for (int i = 0; i < 4; i++) {
            const int idx = tid + i * 128;
            const int r = idx >> 3, c = idx & 7;
            CP_ASYNC16(st + (uint32_t)(r * ROWB + c * 16),
                       (const void*)(A + (size_t)(m0 + r) * 512 + k0 + c * 8));
        }
#pragma unroll
        for (int i = 0; i < 8; i++) {
            const int idx = tid + i * 128;
            const int r = idx >> 3, c = idx & 7;
            const int wr = (r & 1) ? (512 + nb + (r >> 1)) : (nb + (r >> 1));
            CP_ASYNC16(st + (uint32_t)(ARR_A + r * ROWB + c * 16),
                       (const void*)(B + (size_t)wr * 512 + k0 + c * 8));
        }
        CP_COMMIT();
    };

    load_stage(0, 0);

    for (int j = 0; j < 8; j++) {
        CP_WAIT(0);
        __syncthreads();
        if (j + 1 < 8) load_stage(j + 1, (j + 1) & 1);

        const uint32_t st = sbase + (j & 1) * STG_B;
#pragma unroll
        for (int s = 0; s < 4; s++) {
            const uint32_t sk = st + (uint32_t)(s * 32);
            uint32_t bh[4][2], ah[4][4];
            LDMX4(bh[0][0], bh[0][1], bh[1][0], bh[1][1], sk + b_off[0]);
            LDMX4(bh[2][0], bh[2][1], bh[3][0], bh[3][1], sk + b_off[1]);
#pragma unroll
            for (int mi = 0; mi < 4; mi++)
                LDMX4(ah[mi][0], ah[mi][1], ah[mi][2], ah[mi][3], sk + a_off[mi]);
#pragma unroll
            for (int mi = 0; mi < 4; mi++)
#pragma unroll
                for (int ni = 0; ni < 4; ni++)
                    MMA16816(acc[mi][ni][0], acc[mi][ni][1], acc[mi][ni][2], acc[mi][ni][3],
                             ah[mi][0], ah[mi][1], ah[mi][2], ah[mi][3],
                             bh[ni][0], bh[ni][1]);
        }
    }
    __syncthreads();
}

// ---------------------------------------------------------------------------
// GEMM1: hg = x @ W_hg^T, fused lc/lv epilogue (interleaved 16B fp16
// records) + half-chunk summaries. Block = 64 m-rows x 64 channels.
// Grid (8, 1024). 4 CTAs/SM.
// ---------------------------------------------------------------------------
__global__ __launch_bounds__(128, 4)
void gemm1_mma() {
    extern __shared__ __align__(128) char smem[];
    const uint32_t sbase = smem_u32(smem);
    const int m0 = blockIdx.y * 64;
    const int nb = blockIdx.x * 64;

    float acc[4][4][4];
    gemm1_mainloop(g_xh, g_wh, m0, nb, sbase, acc);

    float* lcs = (float*)smem;                      // [64][76]
    float* lvs = lcs + 64 * 76;                     // [64][76]
    float* segA  = (float*)(smem + 40960);          // [2][64]
    float* segLV = segA + 128;                      // [2][64]
    const int tid = threadIdx.x, lane = tid & 31, wid = tid >> 5;
    const int wn = wid * 32;

#pragma unroll
    for (int mi = 0; mi < 4; mi++) {
#pragma unroll
        for (int ni = 0; ni < 4; ni++) {
            const int j  = (wn >> 1) + ni * 4 + (lane & 3);   // channel 0..63
            const int r0 = mi * 16 + (lane >> 2);
#pragma unroll
            for (int e = 0; e < 2; e++) {
                const int r = r0 + e * 8;
                const float hv = acc[mi][ni][2*e];
                const float gv = acc[mi][ni][2*e + 1];
                const float lgv = (hv >= 0.0f) ? __logf(hv + 0.5f) : -sp_f(-hv);
                lcs[r * 76 + j] = -sp_f(gv);
                lvs[r * 76 + j] = lgv - sp_f(-gv);
            }
        }
    }
    __syncthreads();

    // Interleaved stores: one 16B record (lc x4, lv x4) per (row, ch-quad)
    for (int idx = tid; idx < 1024; idx += 128) {
        const int r = idx >> 4, q = idx & 15;
        const size_t go = ((size_t)(m0 + r) * HID + nb + q * 4) * 2;
        float4 vc = *(float4*)&lcs[r * 76 + q * 4];
        float4 vv = *(float4*)&lvs[r * 76 + q * 4];
        __half2 rec[4] = { __floats2half2_rn(vc.x, vc.y), __floats2half2_rn(vc.z, vc.w),
                           __floats2half2_rn(vv.x, vv.y), __floats2half2_rn(vv.z, vv.w) };
        *(uint4*)(g_lcv + go) = *(uint4*)rec;
    }

    // Fused scan summaries: per half-chunk (A, LV). 2 segments of 32 rows.
    {
        const int j = tid & 63, seg = tid >> 6;
        float Acc = 0.0f, LV = -1e30f;
        for (int r = seg * 32; r < seg * 32 + 32; r++) {
            const float lc = lcs[r * 76 + j];
            const float lv = lvs[r * 76 + j];
            LV = lae(lc + LV, lv);
            Acc += lc;
        }
        segA [seg * 64 + j] = Acc;
        segLV[seg * 64 + j] = LV;
    }
    __syncthreads();
    if (tid < 64) {
        const float A2  = segA [64 + tid];
        const float LV2 = segLV[64 + tid];
        float Acc = segA[tid] + A2;
        float LV  = lae(segLV[tid] + A2, LV2);
        const int b = m0 / SEQ, hc = (m0 % SEQ) / HCH;
        const size_t si = ((size_t)(b * NHC + hc)) * HID + nb + tid;
        g_A[si]   = Acc;
        g_LVc[si] = LV;
    }
}

// ---------------------------------------------------------------------------
// GEMM2: out = h @ W_out^T. Block 64x128, grid (4, 1024), 4 CTAs/SM.
// ---------------------------------------------------------------------------
__global__ __launch_bounds__(128, 4)
void gemm2_mma(float* __restrict__ out) {
    extern __shared__ __align__(128) char smem[];
    const uint32_t sbase = smem_u32(smem);
    const int m0 = blockIdx.y * 64;
    const int nb = blockIdx.x * 128;

    const int tid  = threadIdx.x;
    const int lane = tid & 31;
    const int wid  = tid >> 5;
    const int wn   = wid * 32;

    float acc[4][4][4];
#pragma unroll
    for (int mi = 0; mi < 4; mi++)
#pragma unroll
        for (int ni = 0; ni < 4; ni++)
#pragma unroll
            for (int e = 0; e < 4; e++) acc[mi][ni][e] = 0.0f;

    uint32_t a_off[4], b_off[2];
#pragma unroll
    for (int mi = 0; mi < 4; mi++)
        a_off[mi] = (uint32_t)((mi * 16 + (lane & 15)) * ROWB
                               + ((lane & 16) ? 16 : 0));
#pragma unroll
    for (int p = 0; p < 2; p++)
        b_off[p] = (uint32_t)(ARR_A
                   + (wn + p * 16 + (lane & 7) + ((lane & 16) ? 8 : 0)) * ROWB
                   + ((lane & 8) ? 16 : 0));

    auto load_stage = [&](int j, int s) {
        const uint32_t st = sbase + s * STG_B;
        const int k0 = j * 64;
#pragma unroll
        for (int i = 0; i < 4; i++) {
            const int idx = tid + i * 128;
            const int r = idx >> 3, c = idx & 7;
            CP_ASYNC16(st + (uint32_t)(r * ROWB + c * 16),
                       (const void*)(g_hh + (size_t)(m0 + r) * 512 + k0 + c * 8));
        }
#pragma unroll
        for (int i = 0; i < 8; i++) {
            const int idx = tid + i * 128;
            const int r = idx >> 3, c = idx & 7;
            CP_ASYNC16(st + (uint32_t)(ARR_A + r * ROWB + c * 16),
                       (const void*)(g_wo + (size_t)(nb + r) * 512 + k0 + c * 8));
        }
        CP_COMMIT();
    };

    load_stage(0, 0);

    for (int j = 0; j < 8; j++) {
        CP_WAIT(0);
        __syncthreads();
        if (j + 1 < 8) load_stage(j + 1, (j + 1) & 1);

        const uint32_t st = sbase + (j & 1) * STG_B;
#pragma unroll
        for (int s = 0; s < 4; s++) {
            const uint32_t sk = st + (uint32_t)(s * 32);
            uint32_t bh[4][2], ah[4][4];
            LDMX4(bh[0][0], bh[0][1], bh[1][0], bh[1][1], sk + b_off[0]);
            LDMX4(bh[2][0], bh[2][1], bh[3][0], bh[3][1], sk + b_off[1]);
#pragma unroll
            for (int mi = 0; mi < 4; mi++)
                LDMX4(ah[mi][0], ah[mi][1], ah[mi][2], ah[mi][3], sk + a_off[mi]);
#pragma unroll
            for (int mi = 0; mi < 4; mi++)
#pragma unroll
                for (int ni = 0; ni < 4; ni++)
                    MMA16816(acc[mi][ni][0], acc[mi][ni][1], acc[mi][ni][2], acc[mi][ni][3],
                             ah[mi][0], ah[mi][1], ah[mi][2], ah[mi][3],
                             bh[ni][0], bh[ni][1]);
        }
    }

#pragma unroll
    for (int mi = 0; mi < 4; mi++) {
#pragma unroll
        for (int ni = 0; ni < 4; ni++) {
            const int col = nb + wn + ni * 8 + (lane & 3) * 2;
            const int r0  = m0 + mi * 16 + (lane >> 2);
            *(float2*)(out + (size_t)r0 * OUTD + col)
                = make_float2(acc[mi][ni][0], acc[mi][ni][1]);
            *(float2*)(out + (size_t)(r0 + 8) * OUTD + col)
                = make_float2(acc[mi][ni][2], acc[mi][ni][3]);
        }
    }
}

// ---------------------------------------------------------------------------
// Scan pass3 (pass2 fused): block = one (batch, half-chunk); 128 threads x 4
// channels. Prefix from L2-resident g_A/g_LVc, then 64-row replay reading
// ONE 16B interleaved lc/lv record per step (software pipelined). fp16 h out.
// ---------------------------------------------------------------------------
__global__ __launch_bounds__(128) void scan_pass3(float* __restrict__ out_hn) {
    const int b = blockIdx.y, cid = blockIdx.x;       // cid 0..127
    const int ch = threadIdx.x * 4;

    // Fused pass2: prefix over half-chunks [0, cid)
    float4 lh = make_float4(-1e30f, -1e30f, -1e30f, -1e30f);
    size_t si = ((size_t)(b * NHC)) * HID + ch;
    for (int c = 0; c < cid; c++, si += HID) {
        const float4 A4 = *(const float4*)(g_A + si);
        const float4 L4 = *(const float4*)(g_LVc + si);
        lh.x = lae(A4.x + lh.x, L4.x);
        lh.y = lae(A4.y + lh.y, L4.y);
        lh.z = lae(A4.z + lh.z, L4.z);
        lh.w = lae(A4.w + lh.w, L4.w);
    }

    // Half-chunk replay, software pipelined, interleaved 16B records
    size_t base  = ((size_t)(b * SEQ + cid * HCH)) * HID + ch;
    size_t rbase = base * 2;
    float4 hv = make_float4(0.f, 0.f, 0.f, 0.f);
    uint4 rec = *(const uint4*)(g_lcv + rbase);
#pragma unroll 4
    for (int t = 0; t < HCH; t++) {
        uint4 nrec;
        if (t + 1 < HCH) nrec = *(const uint4*)(g_lcv + rbase + (size_t)HID * 2);
        const float2 c01 = __half22float2(*(const __half2*)&rec.x);
        const float2 c23 = __half22float2(*(const __half2*)&rec.y);
        const float2 v01 = __half22float2(*(const __half2*)&rec.z);
        const float2 v23 = __half22float2(*(const __half2*)&rec.w);
        lh.x = lae(c01.x + lh.x, v01.x);
        lh.y = lae(c01.y + lh.y, v01.y);
        lh.z = lae(c23.x + lh.z, v23.x);
        lh.w = lae(c23.y + lh.w, v23.y);
        hv.x = __expf(lh.x); hv.y = __expf(lh.y);
        hv.z = __expf(lh.z); hv.w = __expf(lh.w);
        __half2 h2[2] = { __floats2half2_rn(hv.x, hv.y), __floats2half2_rn(hv.z, hv.w) };
        *(uint2*)(g_hh + base) = *(uint2*)h2;
        rec = nrec;
        base += HID;
        rbase += (size_t)HID * 2;
    }
    if (cid == NHC - 1)
        *(float4*)(out_hn + b * HID + ch) = hv;
}

// ---------------------------------------------------------------------------
// Launch. Inputs: x f32 (8,8192,512) | is_init bool(8) | W_hg f32 (1024,512)
// | W_out f32 (512,512). Output: out f32 (B,S,O) ++ h_n f32 (B,1,H).
// ---------------------------------------------------------------------------
extern "C" void kernel_launch(void* const* d_in, const int* in_sizes, int n_in,
                              void* d_out, int out_size) {
    (void)in_sizes; (void)n_in; (void)out_size;
    const float* x    = (const float*)d_in[0];
    const float* Whg  = (const float*)d_in[2];
    const float* Wout = (const float*)d_in[3];
    float* out    = (float*)d_out;
    float* out_hn = out + (size_t)MROWS * OUTD;

    cudaFuncSetAttribute((const void*)gemm1_mma,
                         cudaFuncAttributeMaxDynamicSharedMemorySize, SMEM_G1);
    cudaFuncSetAttribute((const void*)gemm2_mma,
                         cudaFuncAttributeMaxDynamicSharedMemorySize, SMEM_G1);

    // single fused fp16 conversion (x + both weights)
    cvt_all<<<(unsigned)((NX4 + NW4 + NO4) / 256), 256>>>(x, Whg, Wout);

    // GEMM1 (fp16, kc=64, 64x128 tiles, 4 CTAs/SM) + fused lc/lv + summaries
    gemm1_mma<<<dim3(HID / 64, MROWS / 64), 128, SMEM_G1>>>();

    // scan: half-chunk replay with fused prefix (interleaved lc/lv reads)
    scan_pass3<<<dim3(NHC, BATCH), 128>>>(out_hn);

    // GEMM2 (fp16, kc=64, 64x128 tiles, 4 CTAs/SM)
    gemm2_mma<<<dim3(OUTD / 128, MROWS / 64), 128, SMEM_G1>>>(out);
}

// round 17
// speedup vs baseline: 1.0486x; 1.0010x over previous
#include <cuda_runtime.h>
#include <cuda_fp16.h>
#include <cstdint>
#include <math.h>

// Problem dimensions (fixed by the reference)
#define BATCH 8
#define SEQ   8192
#define DIM   512
#define HID   512
#define OUTD  512
#define MROWS (BATCH*SEQ)      // 65536
#define HCH   64               // half-chunk rows (scan granularity)
#define NHC   (SEQ/HCH)        // 128 half-chunks

// ---------------------------------------------------------------------------
// Device scratch (no runtime allocation allowed)
// g_lcv: interleaved lc/lv, 16B record per (row, 4-channel group):
//   [lc0 lc1 lc2 lc3 lv0 lv1 lv2 lv3] (fp16 each) at offset (m*HID+ch)*2
// ---------------------------------------------------------------------------
static __device__ __half g_lcv[(size_t)MROWS*HID*2];    // lc/lv interleaved
static __device__ float g_A  [(size_t)BATCH*NHC*HID];   // half-chunk sum log_coeffs
static __device__ float g_LVc[(size_t)BATCH*NHC*HID];   // half-chunk log-value
static __device__ __half g_xh [(size_t)MROWS*DIM];      // x     (fp16)
static __device__ __half g_hh [(size_t)MROWS*HID];      // h     (fp16)
static __device__ __half g_wh [(size_t)2*HID*DIM];      // W_hg  (fp16)
static __device__ __half g_wo [(size_t)OUTD*HID];       // W_out (fp16)

// ---------------------------------------------------------------------------
// PTX helpers (sm_80+ only; no 'a'-suffix features)
// ---------------------------------------------------------------------------
__device__ __forceinline__ uint32_t smem_u32(const void* p) {
    uint32_t a;
    asm("{ .reg .u64 t; cvta.to.shared.u64 t, %1; cvt.u32.u64 %0, t; }" : "=r"(a) : "l"(p));
    return a;
}

#define CP_ASYNC16(dst, src) \
    asm volatile("cp.async.cg.shared.global [%0], [%1], 16;" :: "r"(dst), "l"(src))
#define CP_COMMIT() asm volatile("cp.async.commit_group;" ::: "memory")
#define CP_WAIT(N)  asm volatile("cp.async.wait_group %0;" :: "n"(N) : "memory")

#define LDMX4(r0, r1, r2, r3, a) \
    asm volatile("ldmatrix.sync.aligned.m8n8.x4.shared.b16 {%0,%1,%2,%3}, [%4];" \
        : "=r"(r0), "=r"(r1), "=r"(r2), "=r"(r3) : "r"(a))

// fp16 MMA, fp32 accumulate
#define MMA16816(c0, c1, c2, c3, a0, a1, a2, a3, b0, b1) \
    asm volatile("mma.sync.aligned.m16n8k16.row.col.f32.f16.f16.f32 " \
        "{%0,%1,%2,%3}, {%4,%5,%6,%7}, {%8,%9}, {%0,%1,%2,%3};" \
        : "+f"(c0), "+f"(c1), "+f"(c2), "+f"(c3) \
        : "r"(a0), "r"(a1), "r"(a2), "r"(a3), "r"(b0), "r"(b1))

// ---------------------------------------------------------------------------
// Math helpers (fast MUFU path)
// ---------------------------------------------------------------------------
__device__ __forceinline__ float lae(float a, float b) {
    float m = fmaxf(a, b);
    return m + __logf(1.0f + __expf(-fabsf(a - b)));
}

// ---------------------------------------------------------------------------
// Single fused fp32 -> fp16 conversion for x, W_hg, W_out
// ---------------------------------------------------------------------------
#define NX4 ((size_t)MROWS*DIM/4)          // 8388608
#define NW4 ((size_t)2*HID*DIM/4)          // 131072
#define NO4 ((size_t)OUTD*HID/4)           // 65536

__global__ __launch_bounds__(256) void cvt_all(const float* __restrict__ x,
                                               const float* __restrict__ Whg,
                                               const float* __restrict__ Wout) {
    const size_t i = (size_t)blockIdx.x * blockDim.x + threadIdx.x;
    const float* src;
    __half* dst;
    size_t k;
    if (i < NX4)            { src = x;    dst = g_xh; k = i; }
    else if (i < NX4 + NW4) { src = Whg;  dst = g_wh; k = i - NX4; }
    else                    { src = Wout; dst = g_wo; k = i - NX4 - NW4; }
    float4 v = ((const float4*)src)[k];
    ((__half2*)dst)[2*k]   = __floats2half2_rn(v.x, v.y);
    ((__half2*)dst)[2*k+1] = __floats2half2_rn(v.z, v.w);
}

// ---------------------------------------------------------------------------
// GEMM1 mainloop: block 64Mx128N, 128 threads (4 warps, warp tile 64x32),
// K=512, kc=64, 2-stage cp.async, 4 CTAs/SM. acc += A*B (fp32 accumulate).
// SMEM stage: A [0,9216)  B [9216,27648), row stride 144B.
// INTERLEAVE: B-tile n-row r -> W_hg row (even: hidden, odd: gate).
// ---------------------------------------------------------------------------
#define ROWB    144
#define ARR_A   (64*ROWB)       // 9216
#define ARR_BT  (128*ROWB)      // 18432
#define STG_B   (ARR_A+ARR_BT)  // 27648
#define SMEM_G1 (2*STG_B)       // 55296

__device__ __forceinline__ void gemm1_mainloop(const __half* __restrict__ A,
                                               const __half* __restrict__ B,
                                               int m0, int nb, uint32_t sbase,
                                               float acc[4][4][4]) {
    const int tid  = threadIdx.x;
    const int lane = tid & 31;
    const int wid  = tid >> 5;
    const int wn   = wid * 32;

#pragma unroll
    for (int mi = 0; mi < 4; mi++)
#pragma unroll
        for (int ni = 0; ni < 4; ni++)
#pragma unroll
            for (int e = 0; e < 4; e++) acc[mi][ni][e] = 0.0f;

    uint32_t a_off[4], b_off[2];
#pragma unroll
    for (int mi = 0; mi < 4; mi++)
        a_off[mi] = (uint32_t)((mi * 16 + (lane & 15)) * ROWB
                               + ((lane & 16) ? 16 : 0));
#pragma unroll
    for (int p = 0; p < 2; p++)
        b_off[p] = (uint32_t)(ARR_A
                   + (wn + p * 16 + (lane & 7) + ((lane & 16) ? 8 : 0)) * ROWB
                   + ((lane & 8) ? 16 : 0));

    auto load_stage = [&](int j, int s) {
        const uint32_t st = sbase + s * STG_B;
        const int k0 = j * 64;
#pragma unroll
        for (int i = 0; i < 4; i++) {
            const int idx = tid + i * 128;
            const int r = idx >> 3, c = idx & 7;
            CP_ASYNC16(st + (uint32_t)(r * ROWB + c * 16),
                       (const void*)(A + (size_t)(m0 + r) * 512 + k0 + c * 8));
        }
#pragma unroll
        for (int i = 0; i < 8; i++) {
            const int idx = tid + i * 128;
            const int r = idx >> 3, c = idx & 7;
            const int wr = (r & 1) ? (512 + nb + (r >> 1)) : (nb + (r >> 1));
            CP_ASYNC16(st + (uint32_t)(ARR_A + r * ROWB + c * 16),
                       (const void*)(B + (size_t)wr * 512 + k0 + c * 8));
        }
        CP_COMMIT();
    };

    load_stage(0, 0);

    for (int j = 0; j < 8; j++) {
        CP_WAIT(0);
        __syncthreads();
        if (j + 1 < 8) load_stage(j + 1, (j + 1) & 1);

        const uint32_t st = sbase + (j & 1) * STG_B;
#pragma unroll
        for (int s = 0; s < 4; s++) {
            const uint32_t sk = st + (uint32_t)(s * 32);
            uint32_t bh[4][2], ah[4][4];
            LDMX4(bh[0][0], bh[0][1], bh[1][0], bh[1][1], sk + b_off[0]);
            LDMX4(bh[2][0], bh[2][1], bh[3][0], bh[3][1], sk + b_off[1]);
#pragma unroll
            for (int mi = 0; mi < 4; mi++)
                LDMX4(ah[mi][0], ah[mi][1], ah[mi][2], ah[mi][3], sk + a_off[mi]);
#pragma unroll
            for (int mi = 0; mi < 4; mi++)
#pragma unroll
                for (int ni = 0; ni < 4; ni++)
                    MMA16816(acc[mi][ni][0], acc[mi][ni][1], acc[mi][ni][2], acc[mi][ni][3],
                             ah[mi][0], ah[mi][1], ah[mi][2], ah[mi][3],
                             bh[ni][0], bh[ni][1]);
        }
    }
    __syncthreads();
}

// ---------------------------------------------------------------------------
// GEMM1: hg = x @ W_hg^T, fused lc/lv epilogue (shared-exp MUFU CSE,
// interleaved 16B fp16 records) + half-chunk summaries.
// Block = 64 m-rows x 64 channels. Grid (8, 1024). 4 CTAs/SM.
// ---------------------------------------------------------------------------
__global__ __launch_bounds__(128, 4)
void gemm1_mma() {
    extern __shared__ __align__(128) char smem[];
    const uint32_t sbase = smem_u32(smem);
    const int m0 = blockIdx.y * 64;
    const int nb = blockIdx.x * 64;

    float acc[4][4][4];
    gemm1_mainloop(g_xh, g_wh, m0, nb, sbase, acc);

    float* lcs = (float*)smem;                      // [64][76]
    float* lvs = lcs + 64 * 76;                     // [64][76]
    float* segA  = (float*)(smem + 40960);          // [2][64]
    float* segLV = segA + 128;                      // [2][64]
    const int tid = threadIdx.x, lane = tid & 31, wid = tid >> 5;
    const int wn = wid * 32;

#pragma unroll
    for (int mi = 0; mi < 4; mi++) {
#pragma unroll
        for (int ni = 0; ni < 4; ni++) {
            const int j  = (wn >> 1) + ni * 4 + (lane & 3);   // channel 0..63
            const int r0 = mi * 16 + (lane >> 2);
#pragma unroll
            for (int e = 0; e < 2; e++) {
                const int r = r0 + e * 8;
                const float hv = acc[mi][ni][2*e];
                const float gv = acc[mi][ni][2*e + 1];
                // Shared-exp softplus pair:
                //  L = log(1+exp(-|g|));  -sp(g) = -max(g,0)-L ; -sp(-g) = min(g,0)-L
                const float L = __logf(1.0f + __expf(-fabsf(gv)));
                // log_g(h): h>=0 -> log(h+0.5); h<0 -> -sp(-h) = h - log(1+exp(h))
                const float lgv = (hv >= 0.0f)
                    ? __logf(hv + 0.5f)
                    : (hv - __logf(1.0f + __expf(hv)));
                lcs[r * 76 + j] = -fmaxf(gv, 0.0f) - L;
                lvs[r * 76 + j] = lgv + fminf(gv, 0.0f) - L;
            }
        }
    }
    __syncthreads();

    // Interleaved stores: one 16B record (lc x4, lv x4) per (row, ch-quad)
    for (int idx = tid; idx < 1024; idx += 128) {
        const int r = idx >> 4, q = idx & 15;
        const size_t go = ((size_t)(m0 + r) * HID + nb + q * 4) * 2;
        float4 vc = *(float4*)&lcs[r * 76 + q * 4];
        float4 vv = *(float4*)&lvs[r * 76 + q * 4];
        __half2 rec[4] = { __floats2half2_rn(vc.x, vc.y), __floats2half2_rn(vc.z, vc.w),
                           __floats2half2_rn(vv.x, vv.y), __floats2half2_rn(vv.z, vv.w) };
        *(uint4*)(g_lcv + go) = *(uint4*)rec;
    }

    // Fused scan summaries: per half-chunk (A, LV). 2 segments of 32 rows.
    {
        const int j = tid & 63, seg = tid >> 6;
        float Acc = 0.0f, LV = -1e30f;
        for (int r = seg * 32; r < seg * 32 + 32; r++) {
            const float lc = lcs[r * 76 + j];
            const float lv = lvs[r * 76 + j];
            LV = lae(lc + LV, lv);
            Acc += lc;
        }
        segA [seg * 64 + j] = Acc;
        segLV[seg * 64 + j] = LV;
    }
    __syncthreads();
    if (tid < 64) {
        const float A2  = segA [64 + tid];
        const float LV2 = segLV[64 + tid];
        float Acc = segA[tid] + A2;
        float LV  = lae(segLV[tid] + A2, LV2);
        const int b = m0 / SEQ, hc = (m0 % SEQ) / HCH;
        const size_t si = ((size_t)(b * NHC + hc)) * HID + nb + tid;
        g_A[si]   = Acc;
        g_LVc[si] = LV;
    }
}

// ---------------------------------------------------------------------------
// GEMM2: out = h @ W_out^T. Block 64x128, grid (4, 1024), 4 CTAs/SM.
// ---------------------------------------------------------------------------
__global__ __launch_bounds__(128, 4)
void gemm2_mma(float* __restrict__ out) {
    extern __shared__ __align__(128) char smem[];
    const uint32_t sbase = smem_u32(smem);
    const int m0 = blockIdx.y * 64;
    const int nb = blockIdx.x * 128;

    const int tid  = threadIdx.x;
    const int lane = tid & 31;
    const int wid  = tid >> 5;
    const int wn   = wid * 32;

    float acc[4][4][4];
#pragma unroll
    for (int mi = 0; mi < 4; mi++)
#pragma unroll
        for (int ni = 0; ni < 4; ni++)
#pragma unroll
            for (int e = 0; e < 4; e++) acc[mi][ni][e] = 0.0f;

    uint32_t a_off[4], b_off[2];
#pragma unroll
    for (int mi = 0; mi < 4; mi++)
        a_off[mi] = (uint32_t)((mi * 16 + (lane & 15)) * ROWB
                               + ((lane & 16) ? 16 : 0));
#pragma unroll
    for (int p = 0; p < 2; p++)
        b_off[p] = (uint32_t)(ARR_A
                   + (wn + p * 16 + (lane & 7) + ((lane & 16) ? 8 : 0)) * ROWB
                   + ((lane & 8) ? 16 : 0));

    auto load_stage = [&](int j, int s) {
        const uint32_t st = sbase + s * STG_B;
        const int k0 = j * 64;
#pragma unroll
        for (int i = 0; i < 4; i++) {
            const int idx = tid + i * 128;
            const int r = idx >> 3, c = idx & 7;
            CP_ASYNC16(st + (uint32_t)(r * ROWB + c * 16),
                       (const void*)(g_hh + (size_t)(m0 + r) * 512 + k0 + c * 8));
        }
#pragma unroll
        for (int i = 0; i < 8; i++) {
            const int idx = tid + i * 128;
            const int r = idx >> 3, c = idx & 7;
            CP_ASYNC16(st + (uint32_t)(ARR_A + r * ROWB + c * 16),
                       (const void*)(g_wo + (size_t)(nb + r) * 512 + k0 + c * 8));
        }
        CP_COMMIT();
    };

    load_stage(0, 0);

    for (int j = 0; j < 8; j++) {
        CP_WAIT(0);
        __syncthreads();
        if (j + 1 < 8) load_stage(j + 1, (j + 1) & 1);

        const uint32_t st = sbase + (j & 1) * STG_B;
#pragma unroll
        for (int s = 0; s < 4; s++) {
            const uint32_t sk = st + (uint32_t)(s * 32);
            uint32_t bh[4][2], ah[4][4];
            LDMX4(bh[0][0], bh[0][1], bh[1][0], bh[1][1], sk + b_off[0]);
            LDMX4(bh[2][0], bh[2][1], bh[3][0], bh[3][1], sk + b_off[1]);
#pragma unroll
            for (int mi = 0; mi < 4; mi++)
                LDMX4(ah[mi][0], ah[mi][1], ah[mi][2], ah[mi][3], sk + a_off[mi]);
#pragma unroll
            for (int mi = 0; mi < 4; mi++)
#pragma unroll
                for (int ni = 0; ni < 4; ni++)
                    MMA16816(acc[mi][ni][0], acc[mi][ni][1], acc[mi][ni][2], acc[mi][ni][3],
                             ah[mi][0], ah[mi][1], ah[mi][2], ah[mi][3],
                             bh[ni][0], bh[ni][1]);
        }
    }

#pragma unroll
    for (int mi = 0; mi < 4; mi++) {
#pragma unroll
        for (int ni = 0; ni < 4; ni++) {
            const int col = nb + wn + ni * 8 + (lane & 3) * 2;
            const int r0  = m0 + mi * 16 + (lane >> 2);
            *(float2*)(out + (size_t)r0 * OUTD + col)
                = make_float2(acc[mi][ni][0], acc[mi][ni][1]);
            *(float2*)(out + (size_t)(r0 + 8) * OUTD + col)
                = make_float2(acc[mi][ni][2], acc[mi][ni][3]);
        }
    }
}

// ---------------------------------------------------------------------------
// Scan pass3 (pass2 fused): block = one (batch, half-chunk); 128 threads x 4
// channels. Prefix (x2 unrolled) from L2-resident g_A/g_LVc, then 64-row
// replay reading ONE 16B interleaved lc/lv record per step (software
// pipelined). fp16 h out.
// ---------------------------------------------------------------------------
__global__ __launch_bounds__(128) void scan_pass3(float* __restrict__ out_hn) {
    const int b = blockIdx.y, cid = blockIdx.x;       // cid 0..127
    const int ch = threadIdx.x * 4;

    // Fused pass2: prefix over half-chunks [0, cid)
    float4 lh = make_float4(-1e30f, -1e30f, -1e30f, -1e30f);
    size_t si = ((size_t)(b * NHC)) * HID + ch;
#pragma unroll 2
    for (int c = 0; c < cid; c++, si += HID) {
        const float4 A4 = *(const float4*)(g_A + si);
        const float4 L4 = *(const float4*)(g_LVc + si);
        lh.x = lae(A4.x + lh.x, L4.x);
        lh.y = lae(A4.y + lh.y, L4.y);
        lh.z = lae(A4.z + lh.z, L4.z);
        lh.w = lae(A4.w + lh.w, L4.w);
    }

    // Half-chunk replay, software pipelined, interleaved 16B records
    size_t base  = ((size_t)(b * SEQ + cid * HCH)) * HID + ch;
    size_t rbase = base * 2;
    float4 hv = make_float4(0.f, 0.f, 0.f, 0.f);
    uint4 rec = *(const uint4*)(g_lcv + rbase);
#pragma unroll 4
    for (int t = 0; t < HCH; t++) {
        uint4 nrec;
        if (t + 1 < HCH) nrec = *(const uint4*)(g_lcv + rbase + (size_t)HID * 2);
        const float2 c01 = __half22float2(*(const __half2*)&rec.x);
        const float2 c23 = __half22float2(*(const __half2*)&rec.y);
        const float2 v01 = __half22float2(*(const __half2*)&rec.z);
        const float2 v23 = __half22float2(*(const __half2*)&rec.w);
        lh.x = lae(c01.x + lh.x, v01.x);
        lh.y = lae(c01.y + lh.y, v01.y);
        lh.z = lae(c23.x + lh.z, v23.x);
        lh.w = lae(c23.y + lh.w, v23.y);
        hv.x = __expf(lh.x); hv.y = __expf(lh.y);
        hv.z = __expf(lh.z); hv.w = __expf(lh.w);
        __half2 h2[2] = { __floats2half2_rn(hv.x, hv.y), __floats2half2_rn(hv.z, hv.w) };
        *(uint2*)(g_hh + base) = *(uint2*)h2;
        rec = nrec;
        base += HID;
        rbase += (size_t)HID * 2;
    }
    if (cid == NHC - 1)
        *(float4*)(out_hn + b * HID + ch) = hv;
}

// ---------------------------------------------------------------------------
// Launch. Inputs: x f32 (8,8192,512) | is_init bool(8) | W_hg f32 (1024,512)
// | W_out f32 (512,512). Output: out f32 (B,S,O) ++ h_n f32 (B,1,H).
// ---------------------------------------------------------------------------
extern "C" void kernel_launch(void* const* d_in, const int* in_sizes, int n_in,
                              void* d_out, int out_size) {
    (void)in_sizes; (void)n_in; (void)out_size;
    const float* x    = (const float*)d_in[0];
    const float* Whg  = (const float*)d_in[2];
    const float* Wout = (const float*)d_in[3];
    float* out    = (float*)d_out;
    float* out_hn = out + (size_t)MROWS * OUTD;

    cudaFuncSetAttribute((const void*)gemm1_mma,
                         cudaFuncAttributeMaxDynamicSharedMemorySize, SMEM_G1);
    cudaFuncSetAttribute((const void*)gemm2_mma,
                         cudaFuncAttributeMaxDynamicSharedMemorySize, SMEM_G1);

    // single fused fp16 conversion (x + both weights)
    cvt_all<<<(unsigned)((NX4 + NW4 + NO4) / 256), 256>>>(x, Whg, Wout);

    // GEMM1 (fp16, kc=64, 64x128 tiles, 4 CTAs/SM) + fused lc/lv + summaries
    gemm1_mma<<<dim3(HID / 64, MROWS / 64), 128, SMEM_G1>>>();

    // scan: half-chunk replay with fused prefix (interleaved lc/lv reads)
    scan_pass3<<<dim3(NHC, BATCH), 128>>>(out_hn);

    // GEMM2 (fp16, kc=64, 64x128 tiles, 4 CTAs/SM)
    gemm2_mma<<<dim3(OUTD / 128, MROWS / 64), 128, SMEM_G1>>>(out);
}